// round 3
// baseline (speedup 1.0000x reference)
#include <cuda_runtime.h>
#include <math.h>

// ---------------------------------------------------------------------------
// Marching tetrahedra on an implicit regular Kuhn tet grid (DMTetGeometry).
// Output layout (float32, concatenated): verts[E,3], faces[F,3], uvs[N*N*4,2],
// uv_idx[F,3].
//
// Key structural facts (derived from build_tet_grid):
//  - vid(x,y,z) = (x*S + y)*S + z, S = R+1.
//  - All tet edges point along 7 positive lattice directions with vid deltas
//    {1, S, S+1, S^2, S^2+1, S^2+S, S^2+S+1} (ascending).
//  - jnp.unique-sorted crossing-edge order == enumeration by (min vertex a,
//    then delta ascending). So the crossing-edge index is
//    base[a] + popc(mask[a] & lowbits(dir)).
// ---------------------------------------------------------------------------

#define MAXV 274625      // (64+1)^3
#define MAXT 1572864     // 6*64^3
#define MAXPART 1024

__device__ unsigned char g_occ[MAXV];
__device__ unsigned char g_mask[MAXV];
__device__ unsigned      g_cnt[MAXV];
__device__ unsigned      g_base[MAXV];
__device__ unsigned char g_code[MAXT];
__device__ unsigned      g_m1[MAXT];
__device__ unsigned      g_m1e[MAXT];
__device__ unsigned      g_m2[MAXT];
__device__ unsigned      g_m2e[MAXT];
__device__ unsigned      g_part[MAXPART];
__device__ unsigned      g_tot[4];     // [0]=E, [1]=n1, [2]=n2

__constant__ int c_tri_table[16][6] = {
    {-1,-1,-1,-1,-1,-1},{1,0,2,-1,-1,-1},{4,0,3,-1,-1,-1},{1,4,2,1,3,4},
    {3,1,5,-1,-1,-1},{2,3,0,2,5,3},{1,4,0,1,5,4},{4,2,5,-1,-1,-1},
    {4,5,2,-1,-1,-1},{4,1,0,4,5,1},{3,2,0,3,5,2},{1,3,5,-1,-1,-1},
    {4,1,2,4,3,1},{3,0,4,-1,-1,-1},{2,0,1,-1,-1,-1},{-1,-1,-1,-1,-1,-1}};
__constant__ int c_num_tri[16] = {0,1,1,2,1,2,2,1,1,2,2,1,2,1,1,0};
__constant__ int c_kuhn[6][4]  = {{0,1,3,7},{0,2,3,7},{0,1,5,7},
                                  {0,2,6,7},{0,4,5,7},{0,4,6,7}};
__constant__ int c_tedge[6][2] = {{0,1},{0,2},{0,3},{1,2},{1,3},{2,3}};

// -------------------- per-vertex crossing mask ------------------------------
__global__ void k_vertex_mask(const float* __restrict__ sdf, int S, int Nv) {
    int a = blockIdx.x * blockDim.x + threadIdx.x;
    if (a >= Nv) return;
    int S2 = S * S;
    int R  = S - 1;
    int z = a % S;
    int y = (a / S) % S;
    int x = a / S2;
    bool oa = sdf[a] > 0.0f;
    g_occ[a] = (unsigned char)oa;
    int  d[7]  = {1, S, S + 1, S2, S2 + 1, S2 + S, S2 + S + 1};
    bool ok[7] = { z < R, y < R, (y < R && z < R), x < R,
                   (x < R && z < R), (x < R && y < R),
                   (x < R && y < R && z < R) };
    unsigned m = 0;
    #pragma unroll
    for (int k = 0; k < 7; k++) {
        if (ok[k]) {
            bool ob = sdf[a + d[k]] > 0.0f;
            if (ob != oa) m |= (1u << k);
        }
    }
    g_mask[a] = (unsigned char)m;
    g_cnt[a]  = (unsigned)__popc(m);
}

// -------------------- generic exclusive scan (3 kernels) --------------------
__global__ void k_scan_red(const unsigned* __restrict__ in, unsigned* __restrict__ part, int n) {
    __shared__ unsigned sh[256];
    int tid  = threadIdx.x;
    int base = blockIdx.x * 2048 + tid * 8;
    unsigned s = 0;
    #pragma unroll
    for (int i = 0; i < 8; i++) { int idx = base + i; if (idx < n) s += in[idx]; }
    sh[tid] = s; __syncthreads();
    for (int off = 128; off > 0; off >>= 1) {
        if (tid < off) sh[tid] += sh[tid + off];
        __syncthreads();
    }
    if (tid == 0) part[blockIdx.x] = sh[0];
}

__global__ void k_scan_mid(unsigned* __restrict__ part, int nb, int slot) {
    __shared__ unsigned sh[1024];
    int tid = threadIdx.x;
    unsigned v = (tid < nb) ? part[tid] : 0u;
    sh[tid] = v; __syncthreads();
    for (int off = 1; off < 1024; off <<= 1) {
        unsigned add = (tid >= off) ? sh[tid - off] : 0u;
        __syncthreads();
        sh[tid] += add;
        __syncthreads();
    }
    if (tid < nb) part[tid] = sh[tid] - v;   // exclusive
    if (tid == 1023) g_tot[slot] = sh[1023]; // total (padding is zero)
}

__global__ void k_scan_down(const unsigned* __restrict__ in, unsigned* __restrict__ out,
                            const unsigned* __restrict__ part, int n) {
    __shared__ unsigned sh[256];
    int tid  = threadIdx.x;
    int base = blockIdx.x * 2048 + tid * 8;
    unsigned loc[8];
    unsigned s = 0;
    #pragma unroll
    for (int i = 0; i < 8; i++) {
        int idx = base + i;
        loc[i] = (idx < n) ? in[idx] : 0u;
        s += loc[i];
    }
    sh[tid] = s; __syncthreads();
    for (int off = 1; off < 256; off <<= 1) {
        unsigned add = (tid >= off) ? sh[tid - off] : 0u;
        __syncthreads();
        sh[tid] += add;
        __syncthreads();
    }
    unsigned run = part[blockIdx.x] + sh[tid] - s;  // exclusive prefix for this thread
    #pragma unroll
    for (int i = 0; i < 8; i++) {
        int idx = base + i;
        if (idx < n) out[idx] = run;
        run += loc[i];
    }
}

// -------------------- emit interpolated surface vertices --------------------
__global__ void k_emit_verts(const float* __restrict__ verts, const float* __restrict__ sdf,
                             const float* __restrict__ deform, float* __restrict__ out,
                             int S, int Nv, float scale) {
    int a = blockIdx.x * blockDim.x + threadIdx.x;
    if (a >= Nv) return;
    unsigned m = g_mask[a];
    if (!m) return;
    int S2 = S * S;
    int d[7] = {1, S, S + 1, S2, S2 + 1, S2 + S, S2 + S + 1};
    float s0  = sdf[a];
    float pax = verts[3 * a + 0] + scale * tanhf(deform[3 * a + 0]);
    float pay = verts[3 * a + 1] + scale * tanhf(deform[3 * a + 1]);
    float paz = verts[3 * a + 2] + scale * tanhf(deform[3 * a + 2]);
    unsigned idx = g_base[a];
    #pragma unroll
    for (int k = 0; k < 7; k++) {
        if ((m >> k) & 1u) {
            int b = a + d[k];
            float s1 = sdf[b];
            float denom = s0 - s1;
            float w0 = -s1 / denom;
            float w1 =  s0 / denom;
            float bx = verts[3 * b + 0] + scale * tanhf(deform[3 * b + 0]);
            float by = verts[3 * b + 1] + scale * tanhf(deform[3 * b + 1]);
            float bz = verts[3 * b + 2] + scale * tanhf(deform[3 * b + 2]);
            out[3 * idx + 0] = pax * w0 + bx * w1;
            out[3 * idx + 1] = pay * w0 + by * w1;
            out[3 * idx + 2] = paz * w0 + bz * w1;
            idx++;
        }
    }
}

// -------------------- per-tet marching-tets code ----------------------------
__global__ void k_tet_code(int R, int S, int T) {
    int t = blockIdx.x * blockDim.x + threadIdx.x;
    if (t >= T) return;
    int cube = t / 6, k = t % 6;
    int cz = cube % R;
    int cy = (cube / R) % R;
    int cx = cube / (R * R);
    int S2 = S * S;
    int v000 = (cx * S + cy) * S + cz;
    int coff[8] = {0, S2, S, S2 + S, 1, S2 + 1, S + 1, S2 + S + 1};
    int code = 0;
    #pragma unroll
    for (int i = 0; i < 4; i++) {
        int v = v000 + coff[c_kuhn[k][i]];
        code |= ((int)g_occ[v]) << i;
    }
    g_code[t] = (unsigned char)code;
    int nt = c_num_tri[code];
    g_m1[t] = (nt == 1) ? 1u : 0u;
    g_m2[t] = (nt == 2) ? 1u : 0u;
}

// crossing-edge global index of edge (a,b), a<b, along a lattice direction
__device__ __forceinline__ unsigned edge_cross_idx(int a, int b, int S, int S2) {
    int d = b - a;
    int dir;
    if      (d == 1)          dir = 0;
    else if (d == S)          dir = 1;
    else if (d == S + 1)      dir = 2;
    else if (d == S2)         dir = 3;
    else if (d == S2 + 1)     dir = 4;
    else if (d == S2 + S)     dir = 5;
    else                      dir = 6;
    return g_base[a] + (unsigned)__popc((unsigned)g_mask[a] & ((1u << dir) - 1u));
}

// -------------------- faces + uv_idx ----------------------------------------
__global__ void k_faces(float* __restrict__ out, int R, int S, int T, unsigned uvlen) {
    int t = blockIdx.x * blockDim.x + threadIdx.x;
    if (t >= T) return;
    int code = g_code[t];
    int nt = c_num_tri[code];
    if (nt == 0) return;

    unsigned E  = g_tot[0];
    unsigned n1 = g_tot[1];
    unsigned n2 = g_tot[2];
    unsigned F  = n1 + 2u * n2;
    unsigned fbase   = 3u * E;
    unsigned uvibase = 3u * E + 3u * F + uvlen;

    int cube = t / 6, k = t % 6;
    int cz = cube % R;
    int cy = (cube / R) % R;
    int cx = cube / (R * R);
    int S2 = S * S;
    int v000 = (cx * S + cy) * S + cz;
    int coff[8] = {0, S2, S, S2 + S, 1, S2 + 1, S + 1, S2 + S + 1};
    int vv[4];
    #pragma unroll
    for (int i = 0; i < 4; i++) vv[i] = v000 + coff[c_kuhn[k][i]];

    float tg4 = (float)(4u * (unsigned)t);

    if (nt == 1) {
        unsigned row = g_m1e[t];
        #pragma unroll
        for (int c = 0; c < 3; c++) {
            int e = c_tri_table[code][c];
            int a = vv[c_tedge[e][0]], b = vv[c_tedge[e][1]];
            out[fbase + 3u * row + c] = (float)edge_cross_idx(a, b, S, S2);
        }
        out[uvibase + 3u * row + 0] = tg4;
        out[uvibase + 3u * row + 1] = tg4 + 1.0f;
        out[uvibase + 3u * row + 2] = tg4 + 2.0f;
    } else {
        unsigned row0 = n1 + 2u * g_m2e[t];
        #pragma unroll
        for (int c = 0; c < 6; c++) {
            int e = c_tri_table[code][c];
            int a = vv[c_tedge[e][0]], b = vv[c_tedge[e][1]];
            out[fbase + 3u * row0 + c] = (float)edge_cross_idx(a, b, S, S2);
        }
        out[uvibase + 3u * row0 + 0] = tg4;
        out[uvibase + 3u * row0 + 1] = tg4 + 1.0f;
        out[uvibase + 3u * row0 + 2] = tg4 + 2.0f;
        out[uvibase + 3u * row0 + 3] = tg4;
        out[uvibase + 3u * row0 + 4] = tg4 + 2.0f;
        out[uvibase + 3u * row0 + 5] = tg4 + 3.0f;
    }
}

// -------------------- constant uvs section ----------------------------------
__global__ void k_uvs(float* __restrict__ out, int N, float delta, float pad) {
    int c = blockIdx.x * blockDim.x + threadIdx.x;
    if (c >= N * N) return;
    unsigned E = g_tot[0];
    unsigned F = g_tot[1] + 2u * g_tot[2];
    unsigned ub = 3u * E + 3u * F;
    int iy = c / N, ix = c % N;
    float x = (float)ix * delta;
    float y = (float)iy * delta;
    float* p = out + ub + 8u * (unsigned)c;
    p[0] = x;       p[1] = y;
    p[2] = x + pad; p[3] = y;
    p[4] = x + pad; p[5] = y + pad;
    p[6] = x;       p[7] = y + pad;
}

// ---------------------------------------------------------------------------
extern "C" void kernel_launch(void* const* d_in, const int* in_sizes, int n_in,
                              void* d_out, int out_size) {
    const float* verts  = (const float*)d_in[0];
    const float* sdf    = (const float*)d_in[1];
    const float* deform = (const float*)d_in[2];
    float* out = (float*)d_out;

    int Nv = in_sizes[1];                 // sdf element count = (R+1)^3
    int S = 1;
    while (S * S * S < Nv) S++;
    int R = S - 1;
    long T = (long)in_sizes[3] / 4;       // tet count

    // N = ceil(sqrt(T))  (matches map_uv: (2T+1)//2 == T)
    int N = (int)sqrt((double)T);
    while ((long)N * N < T) N++;

    float stopf = (float)(1.0 - 1.0 / (double)N);
    float delta = stopf / (float)(N - 1);
    float pad   = (float)(0.9 / (double)N);
    float scale = 2.0f / (float)(R * 2);
    unsigned uvlen = 8u * (unsigned)N * (unsigned)N;

    void *p_cnt, *p_base, *p_m1, *p_m1e, *p_m2, *p_m2e, *p_part;
    cudaGetSymbolAddress(&p_cnt,  g_cnt);
    cudaGetSymbolAddress(&p_base, g_base);
    cudaGetSymbolAddress(&p_m1,   g_m1);
    cudaGetSymbolAddress(&p_m1e,  g_m1e);
    cudaGetSymbolAddress(&p_m2,   g_m2);
    cudaGetSymbolAddress(&p_m2e,  g_m2e);
    cudaGetSymbolAddress(&p_part, g_part);

    const int B = 256;
    int gV = (Nv + B - 1) / B;
    int gT = (int)((T + B - 1) / B);

    // 1) per-vertex occupancy + crossing mask + counts
    k_vertex_mask<<<gV, B>>>(sdf, S, Nv);

    // 2) exclusive scan of crossing counts -> g_base, total E -> g_tot[0]
    {
        int nb = (Nv + 2047) / 2048;
        k_scan_red <<<nb, 256>>>((const unsigned*)p_cnt, (unsigned*)p_part, Nv);
        k_scan_mid <<<1, 1024>>>((unsigned*)p_part, nb, 0);
        k_scan_down<<<nb, 256>>>((const unsigned*)p_cnt, (unsigned*)p_base,
                                 (const unsigned*)p_part, Nv);
    }

    // 3) interpolated surface vertices (section 0 of out)
    k_emit_verts<<<gV, B>>>(verts, sdf, deform, out, S, Nv, scale);

    // 4) per-tet marching-tets codes + m1/m2 flags
    k_tet_code<<<gT, B>>>(R, S, (int)T);

    // 5) scans for face row assignment: n1 -> g_tot[1], n2 -> g_tot[2]
    {
        int nb = (int)((T + 2047) / 2048);
        k_scan_red <<<nb, 256>>>((const unsigned*)p_m1, (unsigned*)p_part, (int)T);
        k_scan_mid <<<1, 1024>>>((unsigned*)p_part, nb, 1);
        k_scan_down<<<nb, 256>>>((const unsigned*)p_m1, (unsigned*)p_m1e,
                                 (const unsigned*)p_part, (int)T);
        k_scan_red <<<nb, 256>>>((const unsigned*)p_m2, (unsigned*)p_part, (int)T);
        k_scan_mid <<<1, 1024>>>((unsigned*)p_part, nb, 2);
        k_scan_down<<<nb, 256>>>((const unsigned*)p_m2, (unsigned*)p_m2e,
                                 (const unsigned*)p_part, (int)T);
    }

    // 6) faces + uv_idx sections
    k_faces<<<gT, B>>>(out, R, S, (int)T, uvlen);

    // 7) constant uvs section
    int gU = (N * N + B - 1) / B;
    k_uvs<<<gU, B>>>(out, N, delta, pad);
}

// round 4
// speedup vs baseline: 1.1736x; 1.1736x over previous
#include <cuda_runtime.h>
#include <math.h>

// ---------------------------------------------------------------------------
// Marching tetrahedra on an implicit regular Kuhn tet grid (DMTetGeometry).
// Output (float32, concatenated): verts[E,3], faces[F,3], uvs[N*N*4,2],
// uv_idx[F,3].
//
// Structure: 3 fused kernels, decoupled-lookback single-pass scans.
//  K1: per-vertex crossing mask + exclusive scan + surface-vertex emission
//  K2: per-tet MT code + fused (m1,m2) u64 exclusive scan
//  K3: faces + uv_idx + constant uvs
// ---------------------------------------------------------------------------

#define MAXV 274625      // (64+1)^3
#define MAXT 1572864     // 6*64^3
#define TILE 2048        // 256 threads x 8 items
#define NT1  ((MAXV + TILE - 1) / TILE)   // 135
#define NT2  ((MAXT + TILE - 1) / TILE)   // 768
#define M21  ((1ull << 21) - 1ull)
#define M62  ((1ull << 62) - 1ull)

__device__ unsigned char      g_occ[MAXV];
__device__ unsigned char      g_mask[MAXV];
__device__ unsigned           g_base[MAXV];
__device__ unsigned char      g_code[MAXT];
__device__ unsigned long long g_tex[MAXT];        // packed (m2e<<21 | m1e)
__device__ unsigned long long g_state[NT1 + NT2]; // lookback state (memset 0)
__device__ unsigned           g_ticket[2];        // tile tickets (memset 0)
__device__ unsigned           g_tot[4];           // [0]=E, [1]=n1, [2]=n2

__constant__ int c_tri_table[16][6] = {
    {-1,-1,-1,-1,-1,-1},{1,0,2,-1,-1,-1},{4,0,3,-1,-1,-1},{1,4,2,1,3,4},
    {3,1,5,-1,-1,-1},{2,3,0,2,5,3},{1,4,0,1,5,4},{4,2,5,-1,-1,-1},
    {4,5,2,-1,-1,-1},{4,1,0,4,5,1},{3,2,0,3,5,2},{1,3,5,-1,-1,-1},
    {4,1,2,4,3,1},{3,0,4,-1,-1,-1},{2,0,1,-1,-1,-1},{-1,-1,-1,-1,-1,-1}};
__constant__ int c_num_tri[16] = {0,1,1,2,1,2,2,1,1,2,2,1,2,1,1,0};
__constant__ int c_kuhn[6][4]  = {{0,1,3,7},{0,2,3,7},{0,1,5,7},
                                  {0,2,6,7},{0,4,5,7},{0,4,6,7}};
__constant__ int c_tedge[6][2] = {{0,1},{0,2},{0,3},{1,2},{1,3},{2,3}};

// ===========================================================================
// K1: vertex crossing mask + decoupled-lookback scan + vertex emission
// ===========================================================================
__global__ void __launch_bounds__(256)
k1_mask_scan_emit(const float* __restrict__ sdf, const float* __restrict__ verts,
                  const float* __restrict__ deform, float* __restrict__ out,
                  int S, int Nv, float scale, int ntiles) {
    __shared__ unsigned s_tile;
    __shared__ unsigned s_wex[8];
    __shared__ unsigned s_bex;
    if (threadIdx.x == 0) s_tile = atomicAdd(&g_ticket[0], 1u);
    __syncthreads();
    int tile = (int)s_tile;
    int base = tile * TILE + threadIdx.x * 8;
    int S2 = S * S, R = S - 1;
    int d[7] = {1, S, S + 1, S2, S2 + 1, S2 + S, S2 + S + 1};

    unsigned char msk[8];
    unsigned char pre[8];
    unsigned cnt = 0;
    #pragma unroll
    for (int i = 0; i < 8; i++) {
        int a = base + i;
        unsigned m = 0;
        if (a < Nv) {
            int z = a % S;
            int y = (a / S) % S;
            int x = a / S2;
            bool oa = sdf[a] > 0.0f;
            g_occ[a] = (unsigned char)oa;
            bool ok[7] = { z < R, y < R, (y < R && z < R), x < R,
                           (x < R && z < R), (x < R && y < R),
                           (x < R && y < R && z < R) };
            #pragma unroll
            for (int k = 0; k < 7; k++)
                if (ok[k] && ((sdf[a + d[k]] > 0.0f) != oa)) m |= (1u << k);
            g_mask[a] = (unsigned char)m;
        }
        msk[i] = (unsigned char)m;
        pre[i] = (unsigned char)cnt;
        cnt += (unsigned)__popc(m);
    }

    // block scan of per-thread counts
    int lane = threadIdx.x & 31, wid = threadIdx.x >> 5;
    unsigned inc = cnt;
    #pragma unroll
    for (int off = 1; off < 32; off <<= 1) {
        unsigned n = __shfl_up_sync(0xffffffffu, inc, off);
        if (lane >= off) inc += n;
    }
    if (lane == 31) s_wex[wid] = inc;
    __syncthreads();
    if (threadIdx.x == 0) {
        unsigned run = 0;
        #pragma unroll
        for (int w = 0; w < 8; w++) { unsigned t = s_wex[w]; s_wex[w] = run; run += t; }
        unsigned long long agg = run;
        unsigned long long bex = 0;
        if (tile == 0) {
            atomicExch(&g_state[0], (2ull << 62) | agg);
        } else {
            atomicExch(&g_state[tile], (1ull << 62) | agg);
            unsigned long long sum = 0;
            int i = tile - 1;
            while (true) {
                unsigned long long v;
                do { v = *((volatile unsigned long long*)&g_state[i]); } while ((v >> 62) == 0ull);
                sum += v & M62;
                if ((v >> 62) == 2ull) break;
                i--;
            }
            bex = sum;
            atomicExch(&g_state[tile], (2ull << 62) | (bex + agg));
        }
        s_bex = (unsigned)bex;
        if (tile == ntiles - 1) g_tot[0] = (unsigned)(bex + agg);
    }
    __syncthreads();
    unsigned tex = s_bex + s_wex[wid] + (inc - cnt);

    // emit interpolated surface vertices
    #pragma unroll
    for (int i = 0; i < 8; i++) {
        int a = base + i;
        if (a >= Nv) break;
        unsigned ebase = tex + (unsigned)pre[i];
        g_base[a] = ebase;
        unsigned m = msk[i];
        if (!m) continue;
        float s0  = sdf[a];
        float pax = verts[3 * a + 0] + scale * tanhf(deform[3 * a + 0]);
        float pay = verts[3 * a + 1] + scale * tanhf(deform[3 * a + 1]);
        float paz = verts[3 * a + 2] + scale * tanhf(deform[3 * a + 2]);
        unsigned idx = ebase;
        #pragma unroll
        for (int k = 0; k < 7; k++) {
            if ((m >> k) & 1u) {
                int b = a + d[k];
                float s1 = sdf[b];
                float denom = s0 - s1;
                float w0 = -s1 / denom;
                float w1 =  s0 / denom;
                float bx = verts[3 * b + 0] + scale * tanhf(deform[3 * b + 0]);
                float by = verts[3 * b + 1] + scale * tanhf(deform[3 * b + 1]);
                float bz = verts[3 * b + 2] + scale * tanhf(deform[3 * b + 2]);
                out[3 * idx + 0] = pax * w0 + bx * w1;
                out[3 * idx + 1] = pay * w0 + by * w1;
                out[3 * idx + 2] = paz * w0 + bz * w1;
                idx++;
            }
        }
    }
}

// ===========================================================================
// K2: tet code + fused (m1,m2) decoupled-lookback u64 scan
// ===========================================================================
__global__ void __launch_bounds__(256)
k2_code_scan(int R, int S, int T, int ntiles, int state_off) {
    __shared__ unsigned s_tile;
    __shared__ unsigned long long s_wex[8];
    __shared__ unsigned long long s_bex;
    if (threadIdx.x == 0) s_tile = atomicAdd(&g_ticket[1], 1u);
    __syncthreads();
    int tile = (int)s_tile;
    int base = tile * TILE + threadIdx.x * 8;
    int S2 = S * S;

    unsigned char code8[8];
    unsigned long long pre[8];
    unsigned long long sum = 0;
    #pragma unroll
    for (int i = 0; i < 8; i++) {
        int t = base + i;
        int code = 0;
        if (t < T) {
            int cube = t / 6, k = t % 6;
            int cz = cube % R;
            int cy = (cube / R) % R;
            int cx = cube / (R * R);
            int v000 = (cx * S + cy) * S + cz;
            int coff[8] = {0, S2, S, S2 + S, 1, S2 + 1, S + 1, S2 + S + 1};
            #pragma unroll
            for (int j = 0; j < 4; j++)
                code |= ((int)g_occ[v000 + coff[c_kuhn[k][j]]]) << j;
            g_code[t] = (unsigned char)code;
        }
        code8[i] = (unsigned char)code;
        pre[i] = sum;
        int nt = c_num_tri[code];
        if (t < T) {
            if (nt == 1) sum += 1ull;
            else if (nt == 2) sum += (1ull << 21);
        }
    }

    // block scan (u64, two independent 21-bit fields)
    int lane = threadIdx.x & 31, wid = threadIdx.x >> 5;
    unsigned long long inc = sum;
    #pragma unroll
    for (int off = 1; off < 32; off <<= 1) {
        unsigned long long n = __shfl_up_sync(0xffffffffu, inc, off);
        if (lane >= off) inc += n;
    }
    if (lane == 31) s_wex[wid] = inc;
    __syncthreads();
    if (threadIdx.x == 0) {
        unsigned long long run = 0;
        #pragma unroll
        for (int w = 0; w < 8; w++) { unsigned long long t = s_wex[w]; s_wex[w] = run; run += t; }
        unsigned long long agg = run;
        unsigned long long bex = 0;
        unsigned long long* st = g_state + state_off;
        if (tile == 0) {
            atomicExch(&st[0], (2ull << 62) | agg);
        } else {
            atomicExch(&st[tile], (1ull << 62) | agg);
            unsigned long long acc = 0;
            int i = tile - 1;
            while (true) {
                unsigned long long v;
                do { v = *((volatile unsigned long long*)&st[i]); } while ((v >> 62) == 0ull);
                acc += v & M62;
                if ((v >> 62) == 2ull) break;
                i--;
            }
            bex = acc;
            atomicExch(&st[tile], (2ull << 62) | (bex + agg));
        }
        s_bex = bex;
        if (tile == ntiles - 1) {
            unsigned long long tot = bex + agg;
            g_tot[1] = (unsigned)(tot & M21);
            g_tot[2] = (unsigned)((tot >> 21) & M21);
        }
    }
    __syncthreads();
    unsigned long long tex = s_bex + s_wex[wid] + (inc - sum);

    #pragma unroll
    for (int i = 0; i < 8; i++) {
        int t = base + i;
        if (t >= T) break;
        g_tex[t] = tex + pre[i];
        (void)code8[i];
    }
}

// crossing-edge global index of edge (a,b), a<b, along a lattice direction
__device__ __forceinline__ unsigned edge_cross_idx(int a, int b, int S, int S2) {
    int d = b - a;
    int dir;
    if      (d == 1)          dir = 0;
    else if (d == S)          dir = 1;
    else if (d == S + 1)      dir = 2;
    else if (d == S2)         dir = 3;
    else if (d == S2 + 1)     dir = 4;
    else if (d == S2 + S)     dir = 5;
    else                      dir = 6;
    return g_base[a] + (unsigned)__popc((unsigned)g_mask[a] & ((1u << dir) - 1u));
}

// ===========================================================================
// K3: faces + uv_idx + constant uvs (single grid covers both index spaces)
// ===========================================================================
__global__ void __launch_bounds__(256)
k3_faces_uvs(float* __restrict__ out, int R, int S, int T, int N,
             unsigned uvlen, float delta, float pad) {
    int t = blockIdx.x * blockDim.x + threadIdx.x;
    unsigned E  = __ldg(&g_tot[0]);
    unsigned n1 = __ldg(&g_tot[1]);
    unsigned n2 = __ldg(&g_tot[2]);
    unsigned F  = n1 + 2u * n2;
    unsigned fbase   = 3u * E;
    unsigned ub      = 3u * E + 3u * F;          // uvs section start
    unsigned uvibase = ub + uvlen;               // uv_idx section start

    // ---- constant uvs cell ----
    if (t < N * N) {
        int iy = t / N, ix = t % N;
        float x = (float)ix * delta;
        float y = (float)iy * delta;
        float* p = out + ub + 8u * (unsigned)t;
        p[0] = x;       p[1] = y;
        p[2] = x + pad; p[3] = y;
        p[4] = x + pad; p[5] = y + pad;
        p[6] = x;       p[7] = y + pad;
    }

    // ---- face emission ----
    if (t >= T) return;
    int code = g_code[t];
    int nt = c_num_tri[code];
    if (nt == 0) return;

    unsigned long long ex = g_tex[t];
    unsigned m1e = (unsigned)(ex & M21);
    unsigned m2e = (unsigned)((ex >> 21) & M21);

    int cube = t / 6, k = t % 6;
    int cz = cube % R;
    int cy = (cube / R) % R;
    int cx = cube / (R * R);
    int S2 = S * S;
    int v000 = (cx * S + cy) * S + cz;
    int coff[8] = {0, S2, S, S2 + S, 1, S2 + 1, S + 1, S2 + S + 1};
    int vv[4];
    #pragma unroll
    for (int i = 0; i < 4; i++) vv[i] = v000 + coff[c_kuhn[k][i]];

    float tg4 = (float)(4u * (unsigned)t);

    if (nt == 1) {
        unsigned row = m1e;
        #pragma unroll
        for (int c = 0; c < 3; c++) {
            int e = c_tri_table[code][c];
            int a = vv[c_tedge[e][0]], b = vv[c_tedge[e][1]];
            out[fbase + 3u * row + c] = (float)edge_cross_idx(a, b, S, S2);
        }
        out[uvibase + 3u * row + 0] = tg4;
        out[uvibase + 3u * row + 1] = tg4 + 1.0f;
        out[uvibase + 3u * row + 2] = tg4 + 2.0f;
    } else {
        unsigned row0 = n1 + 2u * m2e;
        #pragma unroll
        for (int c = 0; c < 6; c++) {
            int e = c_tri_table[code][c];
            int a = vv[c_tedge[e][0]], b = vv[c_tedge[e][1]];
            out[fbase + 3u * row0 + c] = (float)edge_cross_idx(a, b, S, S2);
        }
        out[uvibase + 3u * row0 + 0] = tg4;
        out[uvibase + 3u * row0 + 1] = tg4 + 1.0f;
        out[uvibase + 3u * row0 + 2] = tg4 + 2.0f;
        out[uvibase + 3u * row0 + 3] = tg4;
        out[uvibase + 3u * row0 + 4] = tg4 + 2.0f;
        out[uvibase + 3u * row0 + 5] = tg4 + 3.0f;
    }
}

// ---------------------------------------------------------------------------
extern "C" void kernel_launch(void* const* d_in, const int* in_sizes, int n_in,
                              void* d_out, int out_size) {
    const float* verts  = (const float*)d_in[0];
    const float* sdf    = (const float*)d_in[1];
    const float* deform = (const float*)d_in[2];
    float* out = (float*)d_out;

    int Nv = in_sizes[1];                 // (R+1)^3
    int S = 1;
    while (S * S * S < Nv) S++;
    int R = S - 1;
    long T = (long)in_sizes[3] / 4;       // tet count

    int N = (int)sqrt((double)T);         // N = ceil(sqrt(T))
    while ((long)N * N < T) N++;

    float stopf = (float)(1.0 - 1.0 / (double)N);
    float delta = stopf / (float)(N - 1);
    float pad   = (float)(0.9 / (double)N);
    float scale = 2.0f / (float)(R * 2);
    unsigned uvlen = 8u * (unsigned)N * (unsigned)N;

    int nt1 = (Nv + TILE - 1) / TILE;
    int nt2 = (int)((T + TILE - 1) / TILE);

    void *p_state, *p_ticket;
    cudaGetSymbolAddress(&p_state,  g_state);
    cudaGetSymbolAddress(&p_ticket, g_ticket);

    // reset lookback state + tickets (tiny, graph-capturable)
    cudaMemsetAsync(p_state, 0, (size_t)(nt1 + nt2) * sizeof(unsigned long long));
    cudaMemsetAsync(p_ticket, 0, 2 * sizeof(unsigned));

    // K1: mask + scan + vertex emission
    k1_mask_scan_emit<<<nt1, 256>>>(sdf, verts, deform, out, S, Nv, scale, nt1);

    // K2: tet codes + fused (m1,m2) scan
    k2_code_scan<<<nt2, 256>>>(R, S, (int)T, nt2, nt1);

    // K3: faces + uv_idx + uvs
    long maxTN = (T > (long)N * N) ? T : (long)N * N;
    int g3 = (int)((maxTN + 255) / 256);
    k3_faces_uvs<<<g3, 256>>>(out, R, S, (int)T, N, uvlen, delta, pad);
}

// round 7
// speedup vs baseline: 1.3924x; 1.1864x over previous
#include <cuda_runtime.h>
#include <math.h>

// ---------------------------------------------------------------------------
// Marching tetrahedra on an implicit regular Kuhn tet grid (DMTetGeometry).
// Output (float32, concatenated): verts[E,3], faces[F,3], uvs[N*N*4,2],
// uv_idx[F,3].
//
// K0: streaming pos = verts + scale*tanh(deform); occ bytes
// K1: per-vertex crossing mask (from occ bytes) + lookback scan + vertex emit
// K2: per-CUBE tet codes (6x4bit packed u32) + fused (m1,m2) lookback scan
// K3: per-tet faces + uv_idx + constant uvs
// ---------------------------------------------------------------------------

#define MAXV 274625              // (64+1)^3
#define MAXC 262144              // 64^3 cubes
#define MAXSTATE 4096
#define M21  ((1ull << 21) - 1ull)
#define M62  ((1ull << 62) - 1ull)

__device__ float              g_pos[3 * MAXV];
__device__ unsigned char      g_occ[MAXV];
__device__ unsigned char      g_mask[MAXV];
__device__ unsigned           g_base[MAXV];
__device__ unsigned           g_ccode[MAXC];      // 6 codes x 4 bits
__device__ unsigned long long g_cpre[MAXC];       // packed (n2<<21 | n1) exclusive prefix
__device__ unsigned long long g_state[MAXSTATE];  // lookback states (memset 0)
__device__ unsigned           g_ticket[2];        // tile tickets (memset 0)
__device__ unsigned           g_tot[4];           // [0]=E, [1]=n1, [2]=n2

__constant__ int c_tri_table[16][6] = {
    {-1,-1,-1,-1,-1,-1},{1,0,2,-1,-1,-1},{4,0,3,-1,-1,-1},{1,4,2,1,3,4},
    {3,1,5,-1,-1,-1},{2,3,0,2,5,3},{1,4,0,1,5,4},{4,2,5,-1,-1,-1},
    {4,5,2,-1,-1,-1},{4,1,0,4,5,1},{3,2,0,3,5,2},{1,3,5,-1,-1,-1},
    {4,1,2,4,3,1},{3,0,4,-1,-1,-1},{2,0,1,-1,-1,-1},{-1,-1,-1,-1,-1,-1}};
__constant__ int c_num_tri[16] = {0,1,1,2,1,2,2,1,1,2,2,1,2,1,1,0};
__constant__ int c_kuhn[6][4]  = {{0,1,3,7},{0,2,3,7},{0,1,5,7},
                                  {0,2,6,7},{0,4,5,7},{0,4,6,7}};
__constant__ int c_tedge[6][2] = {{0,1},{0,2},{0,3},{1,2},{1,3},{2,3}};

// ===========================================================================
// K0: deformed positions (streaming) + occupancy bytes
// ===========================================================================
__global__ void __launch_bounds__(256)
k0_pos_occ(const float* __restrict__ verts, const float* __restrict__ deform,
           const float* __restrict__ sdf, int Nv, float scale) {
    int i = blockIdx.x * blockDim.x + threadIdx.x;
    if (i < 3 * Nv)
        g_pos[i] = verts[i] + scale * tanhf(deform[i]);
    if (i < Nv)
        g_occ[i] = (unsigned char)(sdf[i] > 0.0f);
}

// ===========================================================================
// K1: crossing mask + decoupled-lookback exclusive scan + vertex emission
//     1 vertex / thread, 512-thread blocks (tile = 512)
// ===========================================================================
__global__ void __launch_bounds__(512)
k1_mask_scan_emit(const float* __restrict__ sdf, float* __restrict__ out,
                  int S, int Nv, int ntiles) {
    __shared__ unsigned s_tile;
    __shared__ unsigned s_wex[16];
    __shared__ unsigned s_bex;
    if (threadIdx.x == 0) s_tile = atomicAdd(&g_ticket[0], 1u);
    __syncthreads();
    int tile = (int)s_tile;
    int a = tile * 512 + threadIdx.x;
    int S2 = S * S, R = S - 1;
    int d[7] = {1, S, S + 1, S2, S2 + 1, S2 + S, S2 + S + 1};

    unsigned m = 0;
    if (a < Nv) {
        int z = a % S;
        int y = (a / S) % S;
        int x = a / S2;
        unsigned oa = g_occ[a];
        bool ok[7] = { z < R, y < R, (y < R && z < R), x < R,
                       (x < R && z < R), (x < R && y < R),
                       (x < R && y < R && z < R) };
        #pragma unroll
        for (int k = 0; k < 7; k++)
            if (ok[k] && ((unsigned)g_occ[a + d[k]] != oa)) m |= (1u << k);
        g_mask[a] = (unsigned char)m;
    }
    unsigned cnt = (unsigned)__popc(m);

    // block exclusive scan (512 threads)
    int lane = threadIdx.x & 31, wid = threadIdx.x >> 5;
    unsigned inc = cnt;
    #pragma unroll
    for (int off = 1; off < 32; off <<= 1) {
        unsigned n = __shfl_up_sync(0xffffffffu, inc, off);
        if (lane >= off) inc += n;
    }
    if (lane == 31) s_wex[wid] = inc;
    __syncthreads();
    if (threadIdx.x == 0) {
        unsigned run = 0;
        #pragma unroll
        for (int w = 0; w < 16; w++) { unsigned t = s_wex[w]; s_wex[w] = run; run += t; }
        unsigned long long agg = run;
        unsigned long long bex = 0;
        if (tile == 0) {
            atomicExch(&g_state[0], (2ull << 62) | agg);
        } else {
            atomicExch(&g_state[tile], (1ull << 62) | agg);
            unsigned long long sum = 0;
            int i = tile - 1;
            while (true) {
                unsigned long long v;
                do { v = *((volatile unsigned long long*)&g_state[i]); } while ((v >> 62) == 0ull);
                sum += v & M62;
                if ((v >> 62) == 2ull) break;
                i--;
            }
            bex = sum;
            atomicExch(&g_state[tile], (2ull << 62) | (bex + agg));
        }
        s_bex = (unsigned)bex;
        if (tile == ntiles - 1) g_tot[0] = (unsigned)(bex + agg);
    }
    __syncthreads();
    unsigned ebase = s_bex + s_wex[wid] + (inc - cnt);

    if (a >= Nv) return;
    g_base[a] = ebase;
    if (!m) return;

    // emit interpolated surface vertices from precomputed positions
    float s0  = sdf[a];
    float pax = g_pos[3 * a + 0];
    float pay = g_pos[3 * a + 1];
    float paz = g_pos[3 * a + 2];
    unsigned idx = ebase;
    #pragma unroll
    for (int k = 0; k < 7; k++) {
        if ((m >> k) & 1u) {
            int b = a + d[k];
            float s1 = sdf[b];
            float denom = s0 - s1;
            float w0 = -s1 / denom;
            float w1 =  s0 / denom;
            out[3 * idx + 0] = pax * w0 + g_pos[3 * b + 0] * w1;
            out[3 * idx + 1] = pay * w0 + g_pos[3 * b + 1] * w1;
            out[3 * idx + 2] = paz * w0 + g_pos[3 * b + 2] * w1;
            idx++;
        }
    }
}

// ===========================================================================
// K2: per-cube tet codes + fused (m1,m2) decoupled-lookback u64 scan
//     1 cube / thread, 256-thread blocks (tile = 256)
// ===========================================================================
__global__ void __launch_bounds__(256)
k2_code_scan(int R, int S, int C, int ntiles, int state_off) {
    __shared__ unsigned s_tile;
    __shared__ unsigned long long s_wex[8];
    __shared__ unsigned long long s_bex;
    if (threadIdx.x == 0) s_tile = atomicAdd(&g_ticket[1], 1u);
    __syncthreads();
    int tile = (int)s_tile;
    int c = tile * 256 + threadIdx.x;
    int S2 = S * S;

    unsigned packed_codes = 0;
    unsigned long long cnt = 0;
    if (c < C) {
        int cz = c % R;
        int cy = (c / R) % R;
        int cx = c / (R * R);
        int v000 = (cx * S + cy) * S + cz;
        // corner occ bits (corner i -> delta dx*S2+dy*S+dz per reference offs)
        int coff[8] = {0, S2, S, S2 + S, 1, S2 + 1, S + 1, S2 + S + 1};
        unsigned ob[8];
        #pragma unroll
        for (int i = 0; i < 8; i++) ob[i] = (unsigned)g_occ[v000 + coff[i]];
        #pragma unroll
        for (int k = 0; k < 6; k++) {
            unsigned code = ob[c_kuhn[k][0]] | (ob[c_kuhn[k][1]] << 1)
                          | (ob[c_kuhn[k][2]] << 2) | (ob[c_kuhn[k][3]] << 3);
            packed_codes |= code << (4 * k);
            int nt = c_num_tri[code];
            if (nt == 1)      cnt += 1ull;
            else if (nt == 2) cnt += (1ull << 21);
        }
        g_ccode[c] = packed_codes;
    }

    // block exclusive scan (u64, two 21-bit fields)
    int lane = threadIdx.x & 31, wid = threadIdx.x >> 5;
    unsigned long long inc = cnt;
    #pragma unroll
    for (int off = 1; off < 32; off <<= 1) {
        unsigned long long n = __shfl_up_sync(0xffffffffu, inc, off);
        if (lane >= off) inc += n;
    }
    if (lane == 31) s_wex[wid] = inc;
    __syncthreads();
    if (threadIdx.x == 0) {
        unsigned long long run = 0;
        #pragma unroll
        for (int w = 0; w < 8; w++) { unsigned long long t = s_wex[w]; s_wex[w] = run; run += t; }
        unsigned long long agg = run;
        unsigned long long bex = 0;
        unsigned long long* st = g_state + state_off;
        if (tile == 0) {
            atomicExch(&st[0], (2ull << 62) | agg);
        } else {
            atomicExch(&st[tile], (1ull << 62) | agg);
            unsigned long long acc = 0;
            int i = tile - 1;
            while (true) {
                unsigned long long v;
                do { v = *((volatile unsigned long long*)&st[i]); } while ((v >> 62) == 0ull);
                acc += v & M62;
                if ((v >> 62) == 2ull) break;
                i--;
            }
            bex = acc;
            atomicExch(&st[tile], (2ull << 62) | (bex + agg));
        }
        s_bex = bex;
        if (tile == ntiles - 1) {
            unsigned long long tot = bex + agg;
            g_tot[1] = (unsigned)(tot & M21);
            g_tot[2] = (unsigned)((tot >> 21) & M21);
        }
    }
    __syncthreads();
    if (c < C) g_cpre[c] = s_bex + s_wex[wid] + (inc - cnt);
}

// crossing-edge global index of edge (a,b), a<b, along a lattice direction
__device__ __forceinline__ unsigned edge_cross_idx(int a, int b, int S, int S2) {
    int d = b - a;
    int dir;
    if      (d == 1)          dir = 0;
    else if (d == S)          dir = 1;
    else if (d == S + 1)      dir = 2;
    else if (d == S2)         dir = 3;
    else if (d == S2 + 1)     dir = 4;
    else if (d == S2 + S)     dir = 5;
    else                      dir = 6;
    return g_base[a] + (unsigned)__popc((unsigned)g_mask[a] & ((1u << dir) - 1u));
}

// ===========================================================================
// K3: faces + uv_idx + constant uvs
// ===========================================================================
__global__ void __launch_bounds__(256)
k3_faces_uvs(float* __restrict__ out, int R, int S, int T, int N,
             unsigned uvlen, float delta, float pad) {
    int t = blockIdx.x * blockDim.x + threadIdx.x;
    unsigned E  = g_tot[0];
    unsigned n1 = g_tot[1];
    unsigned n2 = g_tot[2];
    unsigned F  = n1 + 2u * n2;
    unsigned fbase   = 3u * E;
    unsigned ub      = 3u * E + 3u * F;          // uvs section start
    unsigned uvibase = ub + uvlen;               // uv_idx section start

    // ---- constant uvs cell ----
    if (t < N * N) {
        int iy = t / N, ix = t % N;
        float x = (float)ix * delta;
        float y = (float)iy * delta;
        float* p = out + ub + 8u * (unsigned)t;
        p[0] = x;       p[1] = y;
        p[2] = x + pad; p[3] = y;
        p[4] = x + pad; p[5] = y + pad;
        p[6] = x;       p[7] = y + pad;
    }

    // ---- face emission ----
    if (t >= T) return;
    int cube = t / 6;
    int k = t - 6 * cube;
    unsigned codes = g_ccode[cube];
    int code = (int)((codes >> (4 * k)) & 15u);
    int nt = c_num_tri[code];
    if (nt == 0) return;

    unsigned long long pre = g_cpre[cube];
    unsigned m1e = (unsigned)(pre & M21);
    unsigned m2e = (unsigned)((pre >> 21) & M21);
    for (int j = 0; j < k; j++) {
        int cj = (int)((codes >> (4 * j)) & 15u);
        int nj = c_num_tri[cj];
        m1e += (nj == 1);
        m2e += (nj == 2);
    }

    int cz = cube % R;
    int cy = (cube / R) % R;
    int cx = cube / (R * R);
    int S2 = S * S;
    int v000 = (cx * S + cy) * S + cz;
    int coff[8] = {0, S2, S, S2 + S, 1, S2 + 1, S + 1, S2 + S + 1};
    int vv[4];
    #pragma unroll
    for (int i = 0; i < 4; i++) vv[i] = v000 + coff[c_kuhn[k][i]];

    float tg4 = (float)(4u * (unsigned)t);

    if (nt == 1) {
        unsigned row = m1e;
        #pragma unroll
        for (int c = 0; c < 3; c++) {
            int e = c_tri_table[code][c];
            int a = vv[c_tedge[e][0]], b = vv[c_tedge[e][1]];
            out[fbase + 3u * row + c] = (float)edge_cross_idx(a, b, S, S2);
        }
        out[uvibase + 3u * row + 0] = tg4;
        out[uvibase + 3u * row + 1] = tg4 + 1.0f;
        out[uvibase + 3u * row + 2] = tg4 + 2.0f;
    } else {
        unsigned row0 = n1 + 2u * m2e;
        #pragma unroll
        for (int c = 0; c < 6; c++) {
            int e = c_tri_table[code][c];
            int a = vv[c_tedge[e][0]], b = vv[c_tedge[e][1]];
            out[fbase + 3u * row0 + c] = (float)edge_cross_idx(a, b, S, S2);
        }
        out[uvibase + 3u * row0 + 0] = tg4;
        out[uvibase + 3u * row0 + 1] = tg4 + 1.0f;
        out[uvibase + 3u * row0 + 2] = tg4 + 2.0f;
        out[uvibase + 3u * row0 + 3] = tg4;
        out[uvibase + 3u * row0 + 4] = tg4 + 2.0f;
        out[uvibase + 3u * row0 + 5] = tg4 + 3.0f;
    }
}

// ---------------------------------------------------------------------------
extern "C" void kernel_launch(void* const* d_in, const int* in_sizes, int n_in,
                              void* d_out, int out_size) {
    const float* verts  = (const float*)d_in[0];
    const float* sdf    = (const float*)d_in[1];
    const float* deform = (const float*)d_in[2];
    float* out = (float*)d_out;

    int Nv = in_sizes[1];                 // (R+1)^3
    int S = 1;
    while (S * S * S < Nv) S++;
    int R = S - 1;
    int C = R * R * R;                    // cubes
    long T = (long)in_sizes[3] / 4;       // tet count = 6*C

    int N = (int)sqrt((double)T);         // N = ceil(sqrt(T))
    while ((long)N * N < T) N++;

    float stopf = (float)(1.0 - 1.0 / (double)N);
    float delta = stopf / (float)(N - 1);
    float pad   = (float)(0.9 / (double)N);
    float scale = 2.0f / (float)(R * 2);
    unsigned uvlen = 8u * (unsigned)N * (unsigned)N;

    int nt1 = (Nv + 511) / 512;           // K1 tiles
    int nt2 = (C + 255) / 256;            // K2 tiles

    void *p_state, *p_ticket;
    cudaGetSymbolAddress(&p_state,  g_state);
    cudaGetSymbolAddress(&p_ticket, g_ticket);

    cudaMemsetAsync(p_state, 0, (size_t)(nt1 + nt2) * sizeof(unsigned long long));
    cudaMemsetAsync(p_ticket, 0, 2 * sizeof(unsigned));

    // K0: pos + occ (streaming)
    int g0 = (3 * Nv + 255) / 256;
    k0_pos_occ<<<g0, 256>>>(verts, deform, sdf, Nv, scale);

    // K1: mask + scan + vertex emission
    k1_mask_scan_emit<<<nt1, 512>>>(sdf, out, S, Nv, nt1);

    // K2: per-cube codes + fused (m1,m2) scan
    k2_code_scan<<<nt2, 256>>>(R, S, C, nt2, nt1);

    // K3: faces + uv_idx + uvs
    long maxTN = (T > (long)N * N) ? T : (long)N * N;
    int g3 = (int)((maxTN + 255) / 256);
    k3_faces_uvs<<<g3, 256>>>(out, R, S, (int)T, N, uvlen, delta, pad);
}